// round 4
// baseline (speedup 1.0000x reference)
#include <cuda_runtime.h>

// Modulated deformable conv 3x3, in_ch=out_ch=1, stride=1, pad=1, dil=1.
// depth [B,1,H,W], mask [B,9,H,W], offset [B,9,2,H,W] (dy,dx per tap),
// w [1,1,3,3], b [1]. Output [B,1,H,W]. H=W=512 hardcoded.
//
// R4: vertical thread layout. Warp = 32 consecutive x lanes; each thread
// processes 4 rows at its x. Gather LDGs now span ~32px in x -> far fewer
// L1 wavefronts per instruction. Streaming operands scalar but perfectly
// coalesced; distance-1 prefetch pipeline retained.

#define Hc 512
#define Wc 512
#define HWc (Hc * Wc)

__device__ __forceinline__ float bilin_sample(const float* __restrict__ img,
                                              float y, float x) {
    float y0f = floorf(y);
    float x0f = floorf(x);
    float wy = y - y0f;
    float wx = x - x0f;
    int y0 = (int)y0f;
    int x0 = (int)x0f;
    int base = (y0 << 9) + x0;   // W = 512
    bool vy0 = (unsigned)y0 < (unsigned)Hc;
    bool vy1 = (unsigned)(y0 + 1) < (unsigned)Hc;
    bool vx0 = (unsigned)x0 < (unsigned)Wc;
    bool vx1 = (unsigned)(x0 + 1) < (unsigned)Wc;
    float v00 = (vy0 && vx0) ? __ldg(img + base)          : 0.0f;
    float v01 = (vy0 && vx1) ? __ldg(img + base + 1)      : 0.0f;
    float v10 = (vy1 && vx0) ? __ldg(img + base + Wc)     : 0.0f;
    float v11 = (vy1 && vx1) ? __ldg(img + base + Wc + 1) : 0.0f;
    float top = fmaf(wx, v01 - v00, v00);
    float bot = fmaf(wx, v11 - v10, v10);
    return fmaf(wy, bot - top, top);
}

__global__ __launch_bounds__(256)
void dcn_kernel(const float* __restrict__ depth,
                const float* __restrict__ mask,
                const float* __restrict__ off,
                const float* __restrict__ w9,
                const float* __restrict__ bias,
                float* __restrict__ out,
                int B)
{
    // Block decomposition: 256 blocks per image.
    //   block -> (b, ystrip of 4 rows, xstrip of 256 px)
    //   warp  -> xtile of 32 px inside the xstrip
    //   thread -> one x column, 4 rows.
    int lane = threadIdx.x & 31;
    int wrp  = threadIdx.x >> 5;
    int bid  = blockIdx.x;
    int b    = bid >> 8;          // 256 blocks per image
    int rem  = bid & 255;
    int ys   = rem >> 1;          // 128 y-strips of 4 rows
    int xs   = rem & 1;           // 2 x-strips of 256 px
    int y0   = ys << 2;
    int x    = (xs << 8) + (wrp << 5) + lane;

    const float* img   = depth + (size_t)b * HWc;
    const float* mbase = mask  + (size_t)b * 9  * HWc + (y0 << 9) + x;
    const float* obase = off   + (size_t)b * 18 * HWc + (y0 << 9) + x;

    float acc0 = 0.0f, acc1 = 0.0f, acc2 = 0.0f, acc3 = 0.0f;

    float xf = (float)x;

    // Pipeline registers: 12 streaming scalars per tap (dy,dx,m for 4 rows)
    float dy0, dy1, dy2, dy3, dx0, dx1, dx2, dx3, m0, m1, m2, m3;

    // Prologue: tap 0
    dy0 = __ldg(obase + 0 * Wc);  dy1 = __ldg(obase + 1 * Wc);
    dy2 = __ldg(obase + 2 * Wc);  dy3 = __ldg(obase + 3 * Wc);
    dx0 = __ldg(obase + (size_t)HWc + 0 * Wc);
    dx1 = __ldg(obase + (size_t)HWc + 1 * Wc);
    dx2 = __ldg(obase + (size_t)HWc + 2 * Wc);
    dx3 = __ldg(obase + (size_t)HWc + 3 * Wc);
    m0  = __ldg(mbase + 0 * Wc);  m1  = __ldg(mbase + 1 * Wc);
    m2  = __ldg(mbase + 2 * Wc);  m3  = __ldg(mbase + 3 * Wc);

    #pragma unroll
    for (int t = 0; t < 9; t++) {
        // Prefetch tap t+1 streaming operands
        float ndy0, ndy1, ndy2, ndy3, ndx0, ndx1, ndx2, ndx3, nm0, nm1, nm2, nm3;
        if (t < 8) {
            const float* op = obase + (size_t)(2 * t + 2) * HWc;
            const float* xp = obase + (size_t)(2 * t + 3) * HWc;
            const float* mp = mbase + (size_t)(t + 1) * HWc;
            ndy0 = __ldg(op + 0 * Wc); ndy1 = __ldg(op + 1 * Wc);
            ndy2 = __ldg(op + 2 * Wc); ndy3 = __ldg(op + 3 * Wc);
            ndx0 = __ldg(xp + 0 * Wc); ndx1 = __ldg(xp + 1 * Wc);
            ndx2 = __ldg(xp + 2 * Wc); ndx3 = __ldg(xp + 3 * Wc);
            nm0  = __ldg(mp + 0 * Wc); nm1  = __ldg(mp + 1 * Wc);
            nm2  = __ldg(mp + 2 * Wc); nm3  = __ldg(mp + 3 * Wc);
        }

        float wt = __ldg(w9 + t);
        float ybase = (float)(y0 - 1 + t / 3);
        float xtap  = xf + (float)(t % 3 - 1);

        float s;
        s = bilin_sample(img, ybase + 0.0f + dy0, xtap + dx0);
        acc0 = fmaf(s, m0 * wt, acc0);
        s = bilin_sample(img, ybase + 1.0f + dy1, xtap + dx1);
        acc1 = fmaf(s, m1 * wt, acc1);
        s = bilin_sample(img, ybase + 2.0f + dy2, xtap + dx2);
        acc2 = fmaf(s, m2 * wt, acc2);
        s = bilin_sample(img, ybase + 3.0f + dy3, xtap + dx3);
        acc3 = fmaf(s, m3 * wt, acc3);

        if (t < 8) {
            dy0 = ndy0; dy1 = ndy1; dy2 = ndy2; dy3 = ndy3;
            dx0 = ndx0; dx1 = ndx1; dx2 = ndx2; dx3 = ndx3;
            m0  = nm0;  m1  = nm1;  m2  = nm2;  m3  = nm3;
        }
    }

    float bv = __ldg(bias);
    float* optr = out + (size_t)b * HWc + (y0 << 9) + x;
    optr[0 * Wc] = acc0 + bv;
    optr[1 * Wc] = acc1 + bv;
    optr[2 * Wc] = acc2 + bv;
    optr[3 * Wc] = acc3 + bv;
}

extern "C" void kernel_launch(void* const* d_in, const int* in_sizes, int n_in,
                              void* d_out, int out_size)
{
    const float* depth = (const float*)d_in[0];
    const float* mask  = (const float*)d_in[1];
    const float* off   = (const float*)d_in[2];
    const float* w9    = (const float*)d_in[3];
    const float* bias  = (const float*)d_in[4];
    float* out = (float*)d_out;

    int B = in_sizes[0] / HWc;
    int blocks = B * 256;       // 256 blocks per 512x512 image
    dcn_kernel<<<blocks, 256>>>(depth, mask, off, w9, bias, out, B);
}